// round 9
// baseline (speedup 1.0000x reference)
#include <cuda_runtime.h>
#include <cuda_bf16.h>
#include <math.h>

#define BB 64
#define TT 1024
#define MAXLAG 256
#define NT 1024

// Cross-block scratch (device globals — no allocation allowed).
__device__ float g_P[BB];            // per-batch loss
__device__ int   g_done = 0;         // finalize counter (self-resetting)

// Per-warp MSD over 4 consecutive lags [lag0, lag0+3] (lag0 odd).
// Lane handles 2 consecutive positions per iteration: 1 start v2.b64 +
// 3 end v2.b64 (6-value window, 16B-aligned since lag0-1 is even) cover
// 8 point-pairs. Packed fma.rn.f32x2 over (x,y). Results -> fout[0..3].
__device__ __forceinline__ void msd_chunk4(
    unsigned sbase, const float2* s, int L, int lag0, int lane, float* fout)
{
    int np0 = L - lag0;  if (np0 < 0) np0 = 0;
    int np3 = np0 - 3;   if (np3 < 0) np3 = 0;
    const int K = np3 >> 6;

    unsigned addr_a = sbase + 16u * (unsigned)lane;
    unsigned addr_e = sbase + (((unsigned)(lag0 - 1)) << 3) + 16u * (unsigned)lane;
    const unsigned long long NEG1 = 0xBF800000BF800000ULL;   // {-1.f,-1.f}

    unsigned long long acc[4] = {0ull, 0ull, 0ull, 0ull};

    for (int t = 0; t < K; ++t) {
        unsigned long long a0, a1, ev[6], d;
        asm("ld.shared.v2.b64 {%0,%1}, [%2];" : "=l"(a0), "=l"(a1) : "r"(addr_a));
#pragma unroll
        for (int j = 0; j < 3; ++j)
            asm("ld.shared.v2.b64 {%0,%1}, [%2];"
                : "=l"(ev[2 * j]), "=l"(ev[2 * j + 1])
                : "r"(addr_e + 16u * (unsigned)j));
#pragma unroll
        for (int k = 0; k < 4; ++k) {
            asm("fma.rn.f32x2 %0, %1, %2, %3;" : "=l"(d) : "l"(a0), "l"(NEG1), "l"(ev[k + 1]));
            asm("fma.rn.f32x2 %0, %1, %1, %0;" : "+l"(acc[k]) : "l"(d));
            asm("fma.rn.f32x2 %0, %1, %2, %3;" : "=l"(d) : "l"(a1), "l"(NEG1), "l"(ev[k + 2]));
            asm("fma.rn.f32x2 %0, %1, %1, %0;" : "+l"(acc[k]) : "l"(d));
        }
        addr_a += 512;    // 64 positions * 8 B
        addr_e += 512;
    }

#pragma unroll
    for (int k = 0; k < 4; ++k)
        fout[k] = __uint_as_float((unsigned)acc[k]) +
                  __uint_as_float((unsigned)(acc[k] >> 32));

    // Guarded tail: positions [64K, np0), at most ~2 rounds of 32.
    for (int p = (K << 6) + lane; p < np0; p += 32) {
        const float2 a = s[p];
#pragma unroll
        for (int k = 0; k < 4; ++k) {
            if (p < np0 - k) {
                const float2 e = s[p + lag0 + k];
                const float dx = e.x - a.x, dy = e.y - a.y;
                fout[k] = fmaf(dx, dx, fout[k]);
                fout[k] = fmaf(dy, dy, fout[k]);
            }
        }
    }

#pragma unroll
    for (int k = 0; k < 4; ++k) {
#pragma unroll
        for (int o = 16; o; o >>= 1)
            fout[k] += __shfl_xor_sync(0xffffffffu, fout[k], o);
    }
}

// One block per batch, 1024 threads (32 warps, 8/SMSP for latency hiding).
// Warp w owns lag chunks w (lags 4w+1..4w+4) and 63-w (lags 253-4w..256-4w):
// total positions per warp ~= 2L-260, constant => no inter-warp skew.
// MSD results go to SHARED memory; the fit runs in-block after one barrier.
__global__ __launch_bounds__(NT) void physics_kernel(
    const float* __restrict__ traj,
    const float* __restrict__ alpha_pred,
    const int* __restrict__ lengths,
    float* __restrict__ out)
{
    __shared__ __align__(16) float2 s[TT + 2];
    __shared__ float sS[MAXLAG];
    __shared__ float sh[16];
    __shared__ int flag_all;

    const int b = blockIdx.x;
    const float2* tr = reinterpret_cast<const float2*>(traj) + (size_t)b * TT;
    for (int i = threadIdx.x; i < TT; i += NT) s[i] = tr[i];
    __syncthreads();

    const int L    = lengths[b];
    const int w    = threadIdx.x >> 5;
    const int lane = threadIdx.x & 31;
    const unsigned sbase = (unsigned)__cvta_generic_to_shared(s);

    // ---- MSD phase: two balanced 4-lag chunks per warp ----
    const int lagA = 4 * w + 1;              // chunk w
    const int lagB = 4 * (63 - w) + 1;       // chunk 63-w
    float fA[4], fB[4];
    msd_chunk4(sbase, s, L, lagA, lane, fA);
    msd_chunk4(sbase, s, L, lagB, lane, fB);

    if (lane == 0) {
#pragma unroll
        for (int k = 0; k < 4; ++k) {
            sS[(lagA - 1) + k] = fA[k];
            sS[(lagB - 1) + k] = fB[k];
        }
    }
    __syncthreads();

    // ---- in-block fit (threads 0..255; one thread per lag) ----
    const float alpha = alpha_pred[b];
    float resid = 0.f, m = 0.f;
    if (threadIdx.x < MAXLAG) {
        const int il  = threadIdx.x;
        const int lag = il + 1;
        const int np  = L - lag;
        const int cnt = (np > 0) ? np : 1;          // counts = max(#valid, 1)
        const float lm = logf(sS[il] / (float)cnt + 1e-8f);
        const float ll = logf((float)lag);
        m     = (L > lag) ? 1.f : 0.f;
        resid = lm - alpha * ll;
    }

    // reduction 1: sum(resid*m), sum(m)   (warps 8..31 contribute zeros)
    float sr = resid * m, sm = m;
#pragma unroll
    for (int o = 16; o; o >>= 1) {
        sr += __shfl_xor_sync(0xffffffffu, sr, o);
        sm += __shfl_xor_sync(0xffffffffu, sm, o);
    }
    if (lane == 0 && w < 8) { sh[w] = sr; sh[8 + w] = sm; }
    __syncthreads();
    float srt = 0.f, smt = 0.f;
#pragma unroll
    for (int k = 0; k < 8; ++k) { srt += sh[k]; smt += sh[8 + k]; }

    const float denom     = (smt > 1.f) ? smt : 1.f;
    const float intercept = srt / denom;

    // reduction 2: sum((intercept - resid)^2 * m)
    const float dd = (intercept - resid) * m;
    float se = dd * dd;
#pragma unroll
    for (int o = 16; o; o >>= 1) se += __shfl_xor_sync(0xffffffffu, se, o);
    __syncthreads();
    if (lane == 0 && w < 8) sh[w] = se;
    __syncthreads();

    if (threadIdx.x == 0) {
        float t = 0.f;
#pragma unroll
        for (int k = 0; k < 8; ++k) t += sh[k];
        g_P[b] = t / denom;
        __threadfence();                 // publish g_P[b] (1 thread only)
        flag_all = (atomicAdd(&g_done, 1) == BB - 1) ? 1 : 0;
    }
    __syncthreads();
    if (!flag_all) return;

    // ---- globally-last block: mean over batches ----
    if (threadIdx.x < 32) {
        __threadfence();                 // acquire side
        const volatile float* vp = g_P;
        float t = vp[threadIdx.x] + vp[threadIdx.x + 32];
#pragma unroll
        for (int o = 16; o; o >>= 1) t += __shfl_xor_sync(0xffffffffu, t, o);
        if (threadIdx.x == 0) {
            out[0] = t / (float)BB;
            g_done = 0;                  // reset for next graph replay
        }
    }
}

extern "C" void kernel_launch(void* const* d_in, const int* in_sizes, int n_in,
                              void* d_out, int out_size)
{
    const float* alpha_pred = (const float*)d_in[0];
    const float* trajectory = (const float*)d_in[1];
    const int*   lengths    = (const int*)d_in[2];
    float* out = (float*)d_out;

    physics_kernel<<<BB, NT>>>(trajectory, alpha_pred, lengths, out);
}

// round 11
// speedup vs baseline: 1.3039x; 1.3039x over previous
#include <cuda_runtime.h>
#include <cuda_bf16.h>
#include <math.h>

#define BB 64
#define TT 1024
#define MAXLAG 256
#define NT 512

// Cross-block scratch (device globals — no allocation allowed).
__device__ float g_S[BB * MAXLAG];   // per-(batch,lag) sums (each lag fully owned by one block)
__device__ float g_P[BB];            // per-batch loss
__device__ int   g_cnt[BB];          // per-batch arrival counters (self-resetting)
__device__ int   g_done = 0;         // global finalize counter (self-resetting)

// Fused kernel. grid = (64 batches, 4), 512 threads (16 warps) => 256 blocks
// (~32 warps/SM chip-wide). Warp w of block (b,y) owns lags
// lag_k = 4w + y + 1 + 64k (k=0..3): stride-4 interleave => per-block and
// per-warp work balanced to <1%. Main loop unguarded (bounded by largest
// lag's position count); packed fma.rn.f32x2 over (x,y).
// Tail: last block of batch b fits that batch; globally-last block reduces.
__global__ __launch_bounds__(NT) void physics_kernel(
    const float* __restrict__ traj,
    const float* __restrict__ alpha_pred,
    const int* __restrict__ lengths,
    float* __restrict__ out)
{
    __shared__ __align__(16) float2 s[TT];
    __shared__ float sh[16];
    __shared__ int flag_b, flag_all;

    const int b = blockIdx.x;
    const int y = blockIdx.y;

    // 8KB trajectory load: 1 LDG.128 per thread.
    {
        const float4* tr4 = reinterpret_cast<const float4*>(traj) + (size_t)b * (TT / 2);
        float4* s4 = reinterpret_cast<float4*>(s);
        s4[threadIdx.x] = tr4[threadIdx.x];
    }
    __syncthreads();

    const int L    = lengths[b];
    const int w    = threadIdx.x >> 5;
    const int lane = threadIdx.x & 31;

    // ---- MSD phase ----
    const int lam = 4 * w + y + 1;                 // lag_k = lam + 64k
    int np0 = L - lam;          if (np0 < 0) np0 = 0;
    int np1 = np0 - 64;         if (np1 < 0) np1 = 0;
    int np2 = np0 - 128;        if (np2 < 0) np2 = 0;
    int np3 = np0 - 192;        if (np3 < 0) np3 = 0;
    const int K = np3 >> 5;                        // unguarded 32-position rounds

    const unsigned long long* s8 = reinterpret_cast<const unsigned long long*>(s);
    const unsigned long long NEG1 = 0xBF800000BF800000ULL;   // {-1.f,-1.f}
    unsigned long long acc0 = 0, acc1 = 0, acc2 = 0, acc3 = 0;

    {
        int p = lane;
        for (int t = 0; t < K; ++t, p += 32) {
            const unsigned long long a  = s8[p];
            const unsigned long long e0 = s8[p + lam];
            const unsigned long long e1 = s8[p + lam + 64];
            const unsigned long long e2 = s8[p + lam + 128];
            const unsigned long long e3 = s8[p + lam + 192];
            unsigned long long d;
            asm("fma.rn.f32x2 %0, %1, %2, %3;" : "=l"(d) : "l"(a), "l"(NEG1), "l"(e0));
            asm("fma.rn.f32x2 %0, %1, %1, %0;" : "+l"(acc0) : "l"(d));
            asm("fma.rn.f32x2 %0, %1, %2, %3;" : "=l"(d) : "l"(a), "l"(NEG1), "l"(e1));
            asm("fma.rn.f32x2 %0, %1, %1, %0;" : "+l"(acc1) : "l"(d));
            asm("fma.rn.f32x2 %0, %1, %2, %3;" : "=l"(d) : "l"(a), "l"(NEG1), "l"(e2));
            asm("fma.rn.f32x2 %0, %1, %1, %0;" : "+l"(acc2) : "l"(d));
            asm("fma.rn.f32x2 %0, %1, %2, %3;" : "=l"(d) : "l"(a), "l"(NEG1), "l"(e3));
            asm("fma.rn.f32x2 %0, %1, %1, %0;" : "+l"(acc3) : "l"(d));
        }
    }

    float f0 = __uint_as_float((unsigned)acc0) + __uint_as_float((unsigned)(acc0 >> 32));
    float f1 = __uint_as_float((unsigned)acc1) + __uint_as_float((unsigned)(acc1 >> 32));
    float f2 = __uint_as_float((unsigned)acc2) + __uint_as_float((unsigned)(acc2 >> 32));
    float f3 = __uint_as_float((unsigned)acc3) + __uint_as_float((unsigned)(acc3 >> 32));

    // Guarded tail: positions [32K, np0), ~6 rounds of 32 max.
    for (int p = (K << 5) + lane; p < np0; p += 32) {
        const float2 a = s[p];
        {
            const float2 e = s[p + lam];
            const float dx = e.x - a.x, dy = e.y - a.y;
            f0 = fmaf(dx, dx, f0); f0 = fmaf(dy, dy, f0);
        }
        if (p < np1) {
            const float2 e = s[p + lam + 64];
            const float dx = e.x - a.x, dy = e.y - a.y;
            f1 = fmaf(dx, dx, f1); f1 = fmaf(dy, dy, f1);
        }
        if (p < np2) {
            const float2 e = s[p + lam + 128];
            const float dx = e.x - a.x, dy = e.y - a.y;
            f2 = fmaf(dx, dx, f2); f2 = fmaf(dy, dy, f2);
        }
        if (p < np3) {
            const float2 e = s[p + lam + 192];
            const float dx = e.x - a.x, dy = e.y - a.y;
            f3 = fmaf(dx, dx, f3); f3 = fmaf(dy, dy, f3);
        }
    }

#pragma unroll
    for (int o = 16; o; o >>= 1) {
        f0 += __shfl_xor_sync(0xffffffffu, f0, o);
        f1 += __shfl_xor_sync(0xffffffffu, f1, o);
        f2 += __shfl_xor_sync(0xffffffffu, f2, o);
        f3 += __shfl_xor_sync(0xffffffffu, f3, o);
    }
    if (lane == 0) {
        float* dst = &g_S[b * MAXLAG + (lam - 1)];
        dst[0]   = f0;
        dst[64]  = f1;
        dst[128] = f2;
        dst[192] = f3;
        __threadfence();          // writer-side release (16 threads/block only)
    }
    __syncthreads();

    // ---- per-batch arrival; last of the 4 blocks fits batch b ----
    if (threadIdx.x == 0) {
        const int old = atomicAdd(&g_cnt[b], 1);
        flag_b = (old == 3) ? 1 : 0;
        if (old == 3) __threadfence();            // acquire side
    }
    __syncthreads();
    if (!flag_b) return;

    const float alpha = alpha_pred[b];

    float resid = 0.f, m = 0.f;
    if (threadIdx.x < MAXLAG) {
        const int il  = threadIdx.x;
        const int lag = il + 1;
        const int np  = L - lag;
        const int cnt = (np > 0) ? np : 1;        // counts = max(#valid, 1)
        const float S  = __ldcg(&g_S[b * MAXLAG + il]);   // L1-bypass: fresh L2 data
        const float lm = logf(S / (float)cnt + 1e-8f);
        const float ll = logf((float)lag);
        m     = (L > lag) ? 1.f : 0.f;
        resid = lm - alpha * ll;
    }

    // reduction 1: sum(resid*m), sum(m)   (warps 8..15 contribute zeros)
    float sr = resid * m, sm = m;
#pragma unroll
    for (int o = 16; o; o >>= 1) {
        sr += __shfl_xor_sync(0xffffffffu, sr, o);
        sm += __shfl_xor_sync(0xffffffffu, sm, o);
    }
    if (lane == 0 && w < 8) { sh[w] = sr; sh[8 + w] = sm; }
    __syncthreads();
    float srt = 0.f, smt = 0.f;
#pragma unroll
    for (int k = 0; k < 8; ++k) { srt += sh[k]; smt += sh[8 + k]; }

    const float denom     = (smt > 1.f) ? smt : 1.f;
    const float intercept = srt / denom;

    // reduction 2: sum((intercept - resid)^2 * m)
    const float dd = (intercept - resid) * m;
    float se = dd * dd;
#pragma unroll
    for (int o = 16; o; o >>= 1) se += __shfl_xor_sync(0xffffffffu, se, o);
    __syncthreads();
    if (lane == 0 && w < 8) sh[w] = se;
    __syncthreads();

    if (threadIdx.x == 0) {
        float t = 0.f;
#pragma unroll
        for (int k = 0; k < 8; ++k) t += sh[k];
        g_cnt[b] = 0;                       // reset for next graph replay
        g_P[b]   = t / denom;
        __threadfence();                    // publish g_P[b] (1 thread)
        const int old = atomicAdd(&g_done, 1);
        flag_all = (old == BB - 1) ? 1 : 0;
        if (old == BB - 1) __threadfence(); // acquire side
    }
    __syncthreads();
    if (!flag_all) return;

    // ---- globally-last block: mean over batches ----
    if (threadIdx.x < 32) {
        float t = __ldcg(&g_P[threadIdx.x]) + __ldcg(&g_P[threadIdx.x + 32]);
#pragma unroll
        for (int o = 16; o; o >>= 1) t += __shfl_xor_sync(0xffffffffu, t, o);
        if (threadIdx.x == 0) {
            out[0] = t / (float)BB;
            g_done = 0;                     // reset for next graph replay
        }
    }
}

extern "C" void kernel_launch(void* const* d_in, const int* in_sizes, int n_in,
                              void* d_out, int out_size)
{
    const float* alpha_pred = (const float*)d_in[0];
    const float* trajectory = (const float*)d_in[1];
    const int*   lengths    = (const int*)d_in[2];
    float* out = (float*)d_out;

    dim3 g1(BB, 4, 1);
    physics_kernel<<<g1, NT>>>(trajectory, alpha_pred, lengths, out);
}